// round 1
// baseline (speedup 1.0000x reference)
#include <cuda_runtime.h>
#include <cstdint>

// ---------------------------------------------------------------------------
// Problem constants
// ---------------------------------------------------------------------------
#define G_SL   9
#define N_PR   4096
#define D_ORI  2048
#define D_FEAT 512
#define NCLS   21
#define M_TOT  (G_SL * N_PR)          // 36864

// Output layout (flattened tuple, f32):
//   out0: output              [N_PR, 4]          -> 16384
//   out1: delta_pred_offset   [G, N_PR, 4]       -> 147456
//   out2: cls_score_softmax   [G, N_PR, NCLS]    -> 774144
//   out3: alpha_softmax_cls   [G, N_PR, 1]       -> 36864
#define OFF1 (N_PR * 4)
#define OFF2 (OFF1 + G_SL * N_PR * 4)
#define OFF3 (OFF2 + G_SL * N_PR * NCLS)

// ---------------------------------------------------------------------------
// Device scratch (no cudaMalloc allowed)
// ---------------------------------------------------------------------------
__device__ float g_featoff[(size_t)M_TOT * D_FEAT];   // relu(features @ attention_feat), 75.5 MB
__device__ float g_alpha[(size_t)M_TOT * 4];          // alpha logits
__device__ float g_alphacls[(size_t)M_TOT];           // alpha_cls logits

// ---------------------------------------------------------------------------
// Kernel A: C = relu(A @ B)
//   A = features viewed [M_TOT, D_ORI], B = attention_feat [D_ORI, D_FEAT]
// Classic 128x128x8 register-blocked SGEMM, 256 threads, 8x8 per thread.
// ---------------------------------------------------------------------------
#define BM 128
#define BN 128
#define BK 8
#define TM 8
#define TN 8

__global__ __launch_bounds__(256, 2)
void sgemm_relu_kernel(const float* __restrict__ A,
                       const float* __restrict__ B)
{
    __shared__ float As[BK][BM];
    __shared__ float Bs[BK][BN];

    const int bx = blockIdx.x;             // N tile (0..3)
    const int by = blockIdx.y;             // M tile (0..287)
    const int tid = threadIdx.x;

    const int aRow = tid >> 1;             // 0..127
    const int aCol = (tid & 1) * 4;        // 0 or 4
    const int bRow = tid >> 5;             // 0..7
    const int bCol = (tid & 31) * 4;       // 0..124

    const float* Ap = A + ((size_t)(by * BM + aRow)) * D_ORI + aCol;
    const float* Bp = B + (size_t)bRow * D_FEAT + bx * BN + bCol;

    const int tRow = (tid >> 4) * TM;      // 0..120
    const int tCol = (tid & 15) * TN;      // 0..120

    float acc[TM][TN];
#pragma unroll
    for (int i = 0; i < TM; i++)
#pragma unroll
        for (int j = 0; j < TN; j++) acc[i][j] = 0.f;

    for (int k0 = 0; k0 < D_ORI; k0 += BK) {
        float4 a = *reinterpret_cast<const float4*>(Ap);
        Ap += BK;
        As[aCol + 0][aRow] = a.x;
        As[aCol + 1][aRow] = a.y;
        As[aCol + 2][aRow] = a.z;
        As[aCol + 3][aRow] = a.w;

        float4 b = *reinterpret_cast<const float4*>(Bp);
        Bp += (size_t)BK * D_FEAT;
        *reinterpret_cast<float4*>(&Bs[bRow][bCol]) = b;

        __syncthreads();

#pragma unroll
        for (int k = 0; k < BK; k++) {
            float ra[TM], rb[TN];
#pragma unroll
            for (int i = 0; i < TM; i++) ra[i] = As[k][tRow + i];
#pragma unroll
            for (int j = 0; j < TN; j++) rb[j] = Bs[k][tCol + j];
#pragma unroll
            for (int i = 0; i < TM; i++)
#pragma unroll
                for (int j = 0; j < TN; j++)
                    acc[i][j] += ra[i] * rb[j];
        }
        __syncthreads();
    }

    float* Cp = g_featoff + ((size_t)(by * BM + tRow)) * D_FEAT + bx * BN + tCol;
#pragma unroll
    for (int i = 0; i < TM; i++) {
#pragma unroll
        for (int j = 0; j < TN; j += 4) {
            float4 v;
            v.x = fmaxf(acc[i][j + 0], 0.f);
            v.y = fmaxf(acc[i][j + 1], 0.f);
            v.z = fmaxf(acc[i][j + 2], 0.f);
            v.w = fmaxf(acc[i][j + 3], 0.f);
            *reinterpret_cast<float4*>(Cp + (size_t)i * D_FEAT + j) = v;
        }
    }
}

// ---------------------------------------------------------------------------
// Kernel B: per (g, 64-row tile of n):
//   offset[n,0:4]   = features[g,n,:] @ bbox_regress[g]   (2048 x 4)
//   cls[n,0:21]     = features[g,n,:] @ cls_w[g]          (2048 x 21)
//   alpha[n,0:4]    = feat_off[g,n,:] @ alpha_w[g]        (512 x 4)
//   alpha_cls[n]    = feat_off[g,n,:] @ alpha_w_cls[g]    (512 x 1)
// Then: delta_pred_offset written to out1, class softmax to out2,
// alpha / alpha_cls logits to scratch.
// 256 threads = 4 column-groups x 64 rows. Weights staged in smem
// (broadcast reads), features staged in smem (conflict-free via pad).
// ---------------------------------------------------------------------------
#define NPB 64

__global__ __launch_bounds__(256)
void branch_kernel(const float* __restrict__ feats,
                   const float* __restrict__ bbox_w,    // [G, D_ORI, 4]
                   const float* __restrict__ cls_w,     // [G, D_ORI, 21]
                   const float* __restrict__ alpha_w,   // [G, D_FEAT, 4]
                   const float* __restrict__ alpha_w_cls, // [G, D_FEAT, 1]
                   const float* __restrict__ delta_rois,  // [G, N, 5]
                   float* __restrict__ dpo_out,         // out1 [G,N,4]
                   float* __restrict__ cls_out)         // out2 [G,N,21]
{
    const int g  = blockIdx.y;
    const int n0 = blockIdx.x * NPB;
    const int tid = threadIdx.x;
    const int nl = tid & 63;     // local row
    const int cg = tid >> 6;     // column group 0..3

    __shared__ float fS[NPB][65];       // feature tile (padded)
    __shared__ float wS[64][26];        // weight tile (25 cols + zero pad)
    __shared__ float clsS[NPB][22];     // class logits staging

    // column partition: group0: c 0..6, g1: 7..12, g2: 13..18, g3: 19..24
    // c 0..3 = offset, c 4..24 = cls 0..20. Index 25 is zero pad.
    const int c_start_tab[4] = {0, 7, 13, 19};
    const int cs = c_start_tab[cg];

    float acc[7];
#pragma unroll
    for (int i = 0; i < 7; i++) acc[i] = 0.f;

    const float* frow = feats + ((size_t)g * N_PR + n0) * D_ORI;

    // ---- Phase 1: reduce over D_ORI for offset(4) + cls(21) ----
    for (int kc = 0; kc < D_ORI; kc += 64) {
        // stage features [64 rows x 64 k]
        for (int v = tid; v < NPB * 16; v += 256) {
            int rn = v >> 4;
            int k4 = (v & 15) * 4;
            float4 val = *reinterpret_cast<const float4*>(frow + (size_t)rn * D_ORI + kc + k4);
            fS[rn][k4 + 0] = val.x;
            fS[rn][k4 + 1] = val.y;
            fS[rn][k4 + 2] = val.z;
            fS[rn][k4 + 3] = val.w;
        }
        // stage weights [64 k x 26]
        for (int v = tid; v < 64 * 26; v += 256) {
            int k = v / 26;
            int c = v % 26;
            int d = kc + k;
            float w = 0.f;
            if (c < 4)       w = bbox_w[((size_t)g * D_ORI + d) * 4 + c];
            else if (c < 25) w = cls_w[((size_t)g * D_ORI + d) * 21 + (c - 4)];
            wS[k][c] = w;
        }
        __syncthreads();

#pragma unroll 8
        for (int k = 0; k < 64; k++) {
            float f = fS[nl][k];
#pragma unroll
            for (int j = 0; j < 7; j++)
                acc[j] += f * wS[k][cs + j];
        }
        __syncthreads();
    }

    // ---- Phase 2: reduce over D_FEAT for alpha(4) + alpha_cls(1) ----
    float acc2[5] = {0.f, 0.f, 0.f, 0.f, 0.f};
    const float* orow = g_featoff + ((size_t)g * N_PR + n0) * D_FEAT;

    for (int kc = 0; kc < D_FEAT; kc += 64) {
        for (int v = tid; v < NPB * 16; v += 256) {
            int rn = v >> 4;
            int k4 = (v & 15) * 4;
            float4 val = *reinterpret_cast<const float4*>(orow + (size_t)rn * D_FEAT + kc + k4);
            fS[rn][k4 + 0] = val.x;
            fS[rn][k4 + 1] = val.y;
            fS[rn][k4 + 2] = val.z;
            fS[rn][k4 + 3] = val.w;
        }
        for (int v = tid; v < 64 * 5; v += 256) {
            int k = v / 5;
            int c = v % 5;
            int e = kc + k;
            wS[k][c] = (c < 4) ? alpha_w[((size_t)g * D_FEAT + e) * 4 + c]
                               : alpha_w_cls[(size_t)g * D_FEAT + e];
        }
        __syncthreads();

        if (cg == 0) {
#pragma unroll 8
            for (int k = 0; k < 64; k++) {
                float f = fS[nl][k];
#pragma unroll
                for (int j = 0; j < 5; j++)
                    acc2[j] += f * wS[k][j];
            }
        }
        __syncthreads();
    }

    // ---- Epilogue ----
    // stage class logits to smem (cls indices are c-4 in 0..20)
#pragma unroll
    for (int j = 0; j < 7; j++) {
        int c = cs + j;
        if (c >= 4 && c < 25) clsS[nl][c - 4] = acc[j];
    }
    __syncthreads();

    const int n = n0 + nl;
    const size_t gn = (size_t)g * N_PR + n;

    if (cg == 0) {
        // delta_pred_offset = delta_rois[:, :, 1:5] + offset  -> out1
#pragma unroll
        for (int f = 0; f < 4; f++) {
            float dpo = delta_rois[gn * 5 + 1 + f] + acc[f];
            dpo_out[gn * 4 + f] = dpo;
        }
        // alpha / alpha_cls logits -> scratch
#pragma unroll
        for (int f = 0; f < 4; f++) g_alpha[gn * 4 + f] = acc2[f];
        g_alphacls[gn] = acc2[4];
    } else if (cg == 1) {
        // softmax over the 21 classes for row nl -> out2
        float m = clsS[nl][0];
#pragma unroll
        for (int c = 1; c < NCLS; c++) m = fmaxf(m, clsS[nl][c]);
        float e[NCLS];
        float s = 0.f;
#pragma unroll
        for (int c = 0; c < NCLS; c++) {
            e[c] = __expf(clsS[nl][c] - m) ; // fast exp; refined below
        }
        // use accurate expf to stay well inside 1e-3
        s = 0.f;
#pragma unroll
        for (int c = 0; c < NCLS; c++) {
            e[c] = expf(clsS[nl][c] - m);
            s += e[c];
        }
        float inv = 1.f / s;
#pragma unroll
        for (int c = 0; c < NCLS; c++)
            cls_out[gn * NCLS + c] = e[c] * inv;
    }
}

// ---------------------------------------------------------------------------
// Kernel C: softmax over G for alpha and alpha_cls, final weighted sum.
// One thread per proposal n.
// ---------------------------------------------------------------------------
__global__ void finalize_kernel(const float* __restrict__ dpo,  // out1
                                float* __restrict__ out0,       // [N,4]
                                float* __restrict__ out3)       // [G,N]
{
    int n = blockIdx.x * blockDim.x + threadIdx.x;
    if (n >= N_PR) return;

    // regression branch: softmax over G per coord, weighted sum of dpo
#pragma unroll
    for (int f = 0; f < 4; f++) {
        float a[G_SL];
        float m = -1e30f;
#pragma unroll
        for (int g = 0; g < G_SL; g++) {
            a[g] = g_alpha[((size_t)g * N_PR + n) * 4 + f];
            m = fmaxf(m, a[g]);
        }
        float s = 0.f;
#pragma unroll
        for (int g = 0; g < G_SL; g++) {
            a[g] = expf(a[g] - m);
            s += a[g];
        }
        float inv = 1.f / s;
        float o = 0.f;
#pragma unroll
        for (int g = 0; g < G_SL; g++)
            o += dpo[((size_t)g * N_PR + n) * 4 + f] * a[g] * inv;
        out0[(size_t)n * 4 + f] = o;
    }

    // classification alpha: softmax over G
    {
        float a[G_SL];
        float m = -1e30f;
#pragma unroll
        for (int g = 0; g < G_SL; g++) {
            a[g] = g_alphacls[(size_t)g * N_PR + n];
            m = fmaxf(m, a[g]);
        }
        float s = 0.f;
#pragma unroll
        for (int g = 0; g < G_SL; g++) {
            a[g] = expf(a[g] - m);
            s += a[g];
        }
        float inv = 1.f / s;
#pragma unroll
        for (int g = 0; g < G_SL; g++)
            out3[(size_t)g * N_PR + n] = a[g] * inv;
    }
}

// ---------------------------------------------------------------------------
// Launch
// ---------------------------------------------------------------------------
extern "C" void kernel_launch(void* const* d_in, const int* in_sizes, int n_in,
                              void* d_out, int out_size)
{
    const float* features     = (const float*)d_in[0];
    // d_in[1] gt_features  : unused
    // d_in[2] rois         : unused
    const float* delta_rois   = (const float*)d_in[3];
    // d_in[4] ious         : unused
    const float* attention    = (const float*)d_in[5];
    const float* alpha_w      = (const float*)d_in[6];
    const float* bbox_regress = (const float*)d_in[7];
    const float* alpha_w_cls  = (const float*)d_in[8];
    const float* cls_w        = (const float*)d_in[9];

    float* out  = (float*)d_out;
    float* out0 = out;
    float* out1 = out + OFF1;
    float* out2 = out + OFF2;
    float* out3 = out + OFF3;

    // Kernel A: feat_off = relu(features @ attention_feat)
    dim3 gridA(D_FEAT / BN, M_TOT / BM);   // (4, 288)
    sgemm_relu_kernel<<<gridA, 256>>>(features, attention);

    // Kernel B: branch GEMMs + cls softmax + dpo
    dim3 gridB(N_PR / NPB, G_SL);          // (64, 9)
    branch_kernel<<<gridB, 256>>>(features, bbox_regress, cls_w,
                                  alpha_w, alpha_w_cls, delta_rois,
                                  out1, out2);

    // Kernel C: softmax over G + final output
    finalize_kernel<<<(N_PR + 255) / 256, 256>>>(out1, out0, out3);
}

// round 3
// speedup vs baseline: 2.7846x; 2.7846x over previous
#include <cuda_runtime.h>
#include <cstdint>

// ---------------------------------------------------------------------------
// Problem constants
// ---------------------------------------------------------------------------
#define G_SL   9
#define N_PR   4096
#define D_ORI  2048
#define D_FEAT 512
#define NCLS   21
#define M_TOT  (G_SL * N_PR)          // 36864

#define OFF1 (N_PR * 4)
#define OFF2 (OFF1 + G_SL * N_PR * 4)
#define OFF3 (OFF2 + G_SL * N_PR * NCLS)

// ---------------------------------------------------------------------------
// Device scratch (no cudaMalloc allowed)
// ---------------------------------------------------------------------------
__device__ float g_featoff[(size_t)M_TOT * D_FEAT];   // relu(features @ attention_feat)
__device__ float g_Bt[(size_t)D_FEAT * D_ORI];        // attention_feat^T, tf32-rounded
__device__ float g_alpha[(size_t)M_TOT * 4];          // alpha logits
__device__ float g_alphacls[(size_t)M_TOT];           // alpha_cls logits

// ---------------------------------------------------------------------------
// PTX helpers (baseline ISA only — NO tcgen05 on this toolchain target)
// ---------------------------------------------------------------------------
__device__ __forceinline__ uint32_t smem_u32(const void* p) {
    uint32_t a;
    asm("{ .reg .u64 t; cvta.to.shared.u64 t, %1; cvt.u32.u64 %0, t; }"
        : "=r"(a) : "l"(p));
    return a;
}

#define CP_ASYNC16(dst, src) \
    asm volatile("cp.async.cg.shared.global [%0], [%1], 16;" :: "r"(dst), "l"(src) : "memory")
#define CP_COMMIT() asm volatile("cp.async.commit_group;" ::: "memory")

__device__ __forceinline__ uint32_t f2tf(float x) {
    uint32_t u;
    asm("cvt.rna.tf32.f32 %0, %1;" : "=r"(u) : "f"(x));
    return u;
}

__device__ __forceinline__ void mma_tf32(float* c, const uint32_t* a, const uint32_t* b) {
    asm volatile(
        "mma.sync.aligned.m16n8k8.row.col.f32.tf32.tf32.f32 "
        "{%0,%1,%2,%3}, {%4,%5,%6,%7}, {%8,%9}, {%0,%1,%2,%3};"
        : "+f"(c[0]), "+f"(c[1]), "+f"(c[2]), "+f"(c[3])
        : "r"(a[0]), "r"(a[1]), "r"(a[2]), "r"(a[3]),
          "r"(b[0]), "r"(b[1]));
}

// ---------------------------------------------------------------------------
// Pre-kernel: transpose attention_feat [K=2048, N=512] -> g_Bt [N=512, K=2048]
// with round-to-nearest tf32 conversion baked in.
// ---------------------------------------------------------------------------
__global__ void transpose_kernel(const float* __restrict__ B)
{
    __shared__ float tile[32][33];
    const int kx = blockIdx.x * 32;
    const int nx = blockIdx.y * 32;
    const int tx = threadIdx.x, ty = threadIdx.y;   // 32 x 8
#pragma unroll
    for (int j = 0; j < 4; j++)
        tile[ty + j * 8][tx] = B[(size_t)(kx + ty + j * 8) * D_FEAT + nx + tx];
    __syncthreads();
#pragma unroll
    for (int j = 0; j < 4; j++)
        g_Bt[(size_t)(nx + ty + j * 8) * D_ORI + kx + tx] =
            __uint_as_float(f2tf(tile[tx][ty + j * 8]));
}

// ---------------------------------------------------------------------------
// Kernel A: feat_off = relu(features @ attention_feat) via tf32 mma.sync
//   CTA tile M=128, N=128, K=32. 8 warps, warp tile 32x64. 3-stage cp.async.
//   SMEM: As[128][36], Bs[128][36] per stage (pad 36 -> conflict-free frags).
// ---------------------------------------------------------------------------
#define BM 128
#define BN 128
#define BK 32
#define PAD 36
#define NSTAGES 3
#define KITERS (D_ORI / BK)                       // 64
#define A_TILE_BYTES (BM * PAD * 4)               // 18432
#define STAGE_FLOATS ((BM + BN) * PAD)            // 9216
#define STAGE_BYTES  (STAGE_FLOATS * 4)           // 36864
#define SMEM_GEMM_TOTAL (NSTAGES * STAGE_BYTES)   // 110592

__global__ __launch_bounds__(256, 1)
void gemm_tf32_kernel(const float* __restrict__ A)
{
    extern __shared__ float smf[];
    const uint32_t sb = smem_u32(smf);
    const int tid = threadIdx.x;
    const int wid = tid >> 5;
    const int lane = tid & 31;
    const int r  = lane >> 2;     // fragment row group 0..7
    const int cq = lane & 3;      // fragment k quad 0..3

    const int m0 = blockIdx.y * BM;
    const int n0 = blockIdx.x * BN;
    const int mbase = (wid & 3) * 32;
    const int nbase = (wid >> 2) * 64;

    const float* Abase = A + (size_t)m0 * D_ORI;
    const float* Bbase = g_Bt + (size_t)n0 * D_ORI;

    float acc[2][8][4];
#pragma unroll
    for (int mt = 0; mt < 2; mt++)
#pragma unroll
        for (int nt = 0; nt < 8; nt++)
#pragma unroll
            for (int i = 0; i < 4; i++) acc[mt][nt][i] = 0.f;

    auto load_stage = [&](int kiter, int slot) {
        const int k0 = kiter * BK;
        const uint32_t base = sb + slot * STAGE_BYTES;
#pragma unroll
        for (int i = 0; i < 4; i++) {                 // A: 1024 chunks of 16B
            int c = tid + i * 256;
            int row = c >> 3, kc = c & 7;
            CP_ASYNC16(base + row * (PAD * 4) + kc * 16,
                       Abase + (size_t)row * D_ORI + k0 + kc * 4);
        }
#pragma unroll
        for (int i = 0; i < 4; i++) {                 // B: 1024 chunks of 16B
            int c = tid + i * 256;
            int row = c >> 3, kc = c & 7;
            CP_ASYNC16(base + A_TILE_BYTES + row * (PAD * 4) + kc * 16,
                       Bbase + (size_t)row * D_ORI + k0 + kc * 4);
        }
        CP_COMMIT();
    };

    load_stage(0, 0);
    load_stage(1, 1);

    for (int k = 0; k < KITERS; k++) {
        const int slot = k % NSTAGES;

        if (k < KITERS - 2) asm volatile("cp.async.wait_group 1;" ::: "memory");
        else                asm volatile("cp.async.wait_group 0;" ::: "memory");
        __syncthreads();

        if (k + 2 < KITERS) load_stage(k + 2, (k + 2) % NSTAGES);

        const float* As0 = smf + slot * STAGE_FLOATS;
        const float* Bs0 = As0 + BM * PAD;

#pragma unroll
        for (int kk = 0; kk < 4; kk++) {
            uint32_t af[2][4];
#pragma unroll
            for (int mt = 0; mt < 2; mt++) {
                const float* p = As0 + (mbase + mt * 16 + r) * PAD + kk * 8 + cq;
                af[mt][0] = f2tf(p[0]);
                af[mt][1] = f2tf(p[8 * PAD]);
                af[mt][2] = f2tf(p[4]);
                af[mt][3] = f2tf(p[8 * PAD + 4]);
            }
            uint32_t bf[8][2];
#pragma unroll
            for (int nt = 0; nt < 8; nt++) {
                const float* q = Bs0 + (nbase + nt * 8 + r) * PAD + kk * 8 + cq;
                bf[nt][0] = __float_as_uint(q[0]);   // pre-rounded tf32
                bf[nt][1] = __float_as_uint(q[4]);
            }
#pragma unroll
            for (int mt = 0; mt < 2; mt++)
#pragma unroll
                for (int nt = 0; nt < 8; nt++)
                    mma_tf32(acc[mt][nt], af[mt], bf[nt]);
        }
    }

    // Epilogue: relu + store float2 pairs
#pragma unroll
    for (int mt = 0; mt < 2; mt++) {
        const int gr = m0 + mbase + mt * 16 + r;
        float* row0 = g_featoff + (size_t)gr * D_FEAT + n0 + nbase;
        float* row1 = row0 + (size_t)8 * D_FEAT;
#pragma unroll
        for (int nt = 0; nt < 8; nt++) {
            const int col = nt * 8 + cq * 2;
            float2 v0, v1;
            v0.x = fmaxf(acc[mt][nt][0], 0.f);
            v0.y = fmaxf(acc[mt][nt][1], 0.f);
            v1.x = fmaxf(acc[mt][nt][2], 0.f);
            v1.y = fmaxf(acc[mt][nt][3], 0.f);
            *reinterpret_cast<float2*>(row0 + col) = v0;
            *reinterpret_cast<float2*>(row1 + col) = v1;
        }
    }
}

// ---------------------------------------------------------------------------
// Kernel B: branch GEMMs (offset, cls, alpha, alpha_cls) + cls softmax + dpo
//   32-padded weight columns, float4 broadcast weight loads.
// ---------------------------------------------------------------------------
#define NPB 64

__global__ __launch_bounds__(256)
void branch_kernel(const float* __restrict__ feats,
                   const float* __restrict__ bbox_w,      // [G, D_ORI, 4]
                   const float* __restrict__ cls_w,       // [G, D_ORI, 21]
                   const float* __restrict__ alpha_w,     // [G, D_FEAT, 4]
                   const float* __restrict__ alpha_w_cls, // [G, D_FEAT, 1]
                   const float* __restrict__ delta_rois,  // [G, N, 5]
                   float* __restrict__ dpo_out,           // out1 [G,N,4]
                   float* __restrict__ cls_out)           // out2 [G,N,21]
{
    const int g  = blockIdx.y;
    const int n0 = blockIdx.x * NPB;
    const int tid = threadIdx.x;
    const int nl = tid & 63;
    const int cg = tid >> 6;

    __shared__ float fS[NPB][65];
    __shared__ float wS[64][32];
    __shared__ float clsS[NPB][22];

    const int cs = cg * 8;   // columns [cs, cs+8): c<4 offset, 4..24 cls, rest pad

    float acc[8];
#pragma unroll
    for (int i = 0; i < 8; i++) acc[i] = 0.f;

    const float* frow = feats + ((size_t)g * N_PR + n0) * D_ORI;

    for (int kc = 0; kc < D_ORI; kc += 64) {
        for (int v = tid; v < NPB * 16; v += 256) {
            int rn = v >> 4;
            int k4 = (v & 15) * 4;
            float4 val = *reinterpret_cast<const float4*>(frow + (size_t)rn * D_ORI + kc + k4);
            fS[rn][k4 + 0] = val.x;
            fS[rn][k4 + 1] = val.y;
            fS[rn][k4 + 2] = val.z;
            fS[rn][k4 + 3] = val.w;
        }
        for (int v = tid; v < 64 * 32; v += 256) {
            int k = v >> 5;
            int c = v & 31;
            int d = kc + k;
            float w = 0.f;
            if (c < 4)       w = bbox_w[((size_t)g * D_ORI + d) * 4 + c];
            else if (c < 25) w = cls_w[((size_t)g * D_ORI + d) * 21 + (c - 4)];
            wS[k][c] = w;
        }
        __syncthreads();

#pragma unroll 8
        for (int k = 0; k < 64; k++) {
            float f = fS[nl][k];
            float4 w0 = *reinterpret_cast<const float4*>(&wS[k][cs]);
            float4 w1 = *reinterpret_cast<const float4*>(&wS[k][cs + 4]);
            acc[0] += f * w0.x;  acc[1] += f * w0.y;
            acc[2] += f * w0.z;  acc[3] += f * w0.w;
            acc[4] += f * w1.x;  acc[5] += f * w1.y;
            acc[6] += f * w1.z;  acc[7] += f * w1.w;
        }
        __syncthreads();
    }

    // Phase 2: alpha(4) + alpha_cls(1) over D_FEAT (only cg==0 computes)
    float acc2[5] = {0.f, 0.f, 0.f, 0.f, 0.f};
    const float* orow = g_featoff + ((size_t)g * N_PR + n0) * D_FEAT;

    for (int kc = 0; kc < D_FEAT; kc += 64) {
        for (int v = tid; v < NPB * 16; v += 256) {
            int rn = v >> 4;
            int k4 = (v & 15) * 4;
            float4 val = *reinterpret_cast<const float4*>(orow + (size_t)rn * D_FEAT + kc + k4);
            fS[rn][k4 + 0] = val.x;
            fS[rn][k4 + 1] = val.y;
            fS[rn][k4 + 2] = val.z;
            fS[rn][k4 + 3] = val.w;
        }
        for (int v = tid; v < 64 * 8; v += 256) {
            int k = v >> 3;
            int c = v & 7;
            int e = kc + k;
            float w = 0.f;
            if (c < 4)      w = alpha_w[((size_t)g * D_FEAT + e) * 4 + c];
            else if (c == 4) w = alpha_w_cls[(size_t)g * D_FEAT + e];
            wS[k][c] = w;
        }
        __syncthreads();

        if (cg == 0) {
#pragma unroll 8
            for (int k = 0; k < 64; k++) {
                float f = fS[nl][k];
                float4 w0 = *reinterpret_cast<const float4*>(&wS[k][0]);
                acc2[0] += f * w0.x;  acc2[1] += f * w0.y;
                acc2[2] += f * w0.z;  acc2[3] += f * w0.w;
                acc2[4] += f * wS[k][4];
            }
        }
        __syncthreads();
    }

    // stage class logits
#pragma unroll
    for (int j = 0; j < 8; j++) {
        int c = cs + j;
        if (c >= 4 && c < 25) clsS[nl][c - 4] = acc[j];
    }
    __syncthreads();

    const int n = n0 + nl;
    const size_t gn = (size_t)g * N_PR + n;

    if (cg == 0) {
#pragma unroll
        for (int f = 0; f < 4; f++) {
            float dpo = delta_rois[gn * 5 + 1 + f] + acc[f];
            dpo_out[gn * 4 + f] = dpo;
        }
#pragma unroll
        for (int f = 0; f < 4; f++) g_alpha[gn * 4 + f] = acc2[f];
        g_alphacls[gn] = acc2[4];
    } else if (cg == 1) {
        float m = clsS[nl][0];
#pragma unroll
        for (int c = 1; c < NCLS; c++) m = fmaxf(m, clsS[nl][c]);
        float e[NCLS];
        float s = 0.f;
#pragma unroll
        for (int c = 0; c < NCLS; c++) {
            e[c] = expf(clsS[nl][c] - m);
            s += e[c];
        }
        float inv = 1.f / s;
#pragma unroll
        for (int c = 0; c < NCLS; c++)
            cls_out[gn * NCLS + c] = e[c] * inv;
    }
}

// ---------------------------------------------------------------------------
// Kernel C: softmax over G + final weighted sum
// ---------------------------------------------------------------------------
__global__ void finalize_kernel(const float* __restrict__ dpo,
                                float* __restrict__ out0,
                                float* __restrict__ out3)
{
    int n = blockIdx.x * blockDim.x + threadIdx.x;
    if (n >= N_PR) return;

#pragma unroll
    for (int f = 0; f < 4; f++) {
        float a[G_SL];
        float m = -1e30f;
#pragma unroll
        for (int g = 0; g < G_SL; g++) {
            a[g] = g_alpha[((size_t)g * N_PR + n) * 4 + f];
            m = fmaxf(m, a[g]);
        }
        float s = 0.f;
#pragma unroll
        for (int g = 0; g < G_SL; g++) {
            a[g] = expf(a[g] - m);
            s += a[g];
        }
        float inv = 1.f / s;
        float o = 0.f;
#pragma unroll
        for (int g = 0; g < G_SL; g++)
            o += dpo[((size_t)g * N_PR + n) * 4 + f] * a[g] * inv;
        out0[(size_t)n * 4 + f] = o;
    }

    {
        float a[G_SL];
        float m = -1e30f;
#pragma unroll
        for (int g = 0; g < G_SL; g++) {
            a[g] = g_alphacls[(size_t)g * N_PR + n];
            m = fmaxf(m, a[g]);
        }
        float s = 0.f;
#pragma unroll
        for (int g = 0; g < G_SL; g++) {
            a[g] = expf(a[g] - m);
            s += a[g];
        }
        float inv = 1.f / s;
#pragma unroll
        for (int g = 0; g < G_SL; g++)
            out3[(size_t)g * N_PR + n] = a[g] * inv;
    }
}

// ---------------------------------------------------------------------------
// Launch
// ---------------------------------------------------------------------------
extern "C" void kernel_launch(void* const* d_in, const int* in_sizes, int n_in,
                              void* d_out, int out_size)
{
    const float* features     = (const float*)d_in[0];
    const float* delta_rois   = (const float*)d_in[3];
    const float* attention    = (const float*)d_in[5];
    const float* alpha_w      = (const float*)d_in[6];
    const float* bbox_regress = (const float*)d_in[7];
    const float* alpha_w_cls  = (const float*)d_in[8];
    const float* cls_w        = (const float*)d_in[9];

    float* out  = (float*)d_out;
    float* out0 = out;
    float* out1 = out + OFF1;
    float* out2 = out + OFF2;
    float* out3 = out + OFF3;

    static bool attr_set = false;
    if (!attr_set) {
        cudaFuncSetAttribute(gemm_tf32_kernel,
                             cudaFuncAttributeMaxDynamicSharedMemorySize,
                             SMEM_GEMM_TOTAL);
        attr_set = true;
    }

    // Pre: transpose attention_feat to [N, K] (K-major, tf32-rounded)
    transpose_kernel<<<dim3(D_ORI / 32, D_FEAT / 32), dim3(32, 8)>>>(attention);

    // Kernel A: tf32 mma.sync GEMM + relu
    gemm_tf32_kernel<<<dim3(D_FEAT / BN, M_TOT / BM), 256, SMEM_GEMM_TOTAL>>>(features);

    // Kernel B: branch GEMMs + cls softmax + dpo
    branch_kernel<<<dim3(N_PR / NPB, G_SL), 256>>>(features, bbox_regress, cls_w,
                                                   alpha_w, alpha_w_cls, delta_rois,
                                                   out1, out2);

    // Kernel C: softmax over G + final output
    finalize_kernel<<<(N_PR + 255) / 256, 256>>>(out1, out0, out3);
}

// round 4
// speedup vs baseline: 3.8155x; 1.3702x over previous
#include <cuda_runtime.h>
#include <cstdint>

// ---------------------------------------------------------------------------
// Problem constants
// ---------------------------------------------------------------------------
#define G_SL   9
#define N_PR   4096
#define D_ORI  2048
#define D_FEAT 512
#define NCLS   21
#define M_TOT  (G_SL * N_PR)          // 36864

#define OFF1 (N_PR * 4)
#define OFF2 (OFF1 + G_SL * N_PR * 4)
#define OFF3 (OFF2 + G_SL * N_PR * NCLS)

// ---------------------------------------------------------------------------
// Device scratch (no cudaMalloc allowed)
// ---------------------------------------------------------------------------
__device__ float g_Bt[(size_t)D_FEAT * D_ORI];   // attention_feat^T, tf32-rounded
__device__ float g_alpha[(size_t)M_TOT * 4];     // alpha logits (atomic accum)
__device__ float g_alphacls[(size_t)M_TOT];      // alpha_cls logits (atomic accum)

// ---------------------------------------------------------------------------
// PTX helpers (baseline ISA only — NO tcgen05 on this toolchain target)
// ---------------------------------------------------------------------------
__device__ __forceinline__ uint32_t smem_u32(const void* p) {
    uint32_t a;
    asm("{ .reg .u64 t; cvta.to.shared.u64 t, %1; cvt.u32.u64 %0, t; }"
        : "=r"(a) : "l"(p));
    return a;
}

#define CP_ASYNC16(dst, src) \
    asm volatile("cp.async.cg.shared.global [%0], [%1], 16;" :: "r"(dst), "l"(src) : "memory")
#define CP_COMMIT() asm volatile("cp.async.commit_group;" ::: "memory")

__device__ __forceinline__ uint32_t f2tf(float x) {
    uint32_t u;
    asm("cvt.rna.tf32.f32 %0, %1;" : "=r"(u) : "f"(x));
    return u;
}

__device__ __forceinline__ void mma_tf32(float* c, const uint32_t* a, const uint32_t* b) {
    asm volatile(
        "mma.sync.aligned.m16n8k8.row.col.f32.tf32.tf32.f32 "
        "{%0,%1,%2,%3}, {%4,%5,%6,%7}, {%8,%9}, {%0,%1,%2,%3};"
        : "+f"(c[0]), "+f"(c[1]), "+f"(c[2]), "+f"(c[3])
        : "r"(a[0]), "r"(a[1]), "r"(a[2]), "r"(a[3]),
          "r"(b[0]), "r"(b[1]));
}

// ---------------------------------------------------------------------------
// Pre-kernel: transpose attention_feat [K=2048, N=512] -> g_Bt [N=512, K=2048]
// tf32-rounded.
// ---------------------------------------------------------------------------
__global__ void transpose_kernel(const float* __restrict__ B)
{
    __shared__ float tile[32][33];
    const int kx = blockIdx.x * 32;
    const int nx = blockIdx.y * 32;
    const int tx = threadIdx.x, ty = threadIdx.y;   // 32 x 8
#pragma unroll
    for (int j = 0; j < 4; j++)
        tile[ty + j * 8][tx] = B[(size_t)(kx + ty + j * 8) * D_FEAT + nx + tx];
    __syncthreads();
#pragma unroll
    for (int j = 0; j < 4; j++)
        g_Bt[(size_t)(nx + ty + j * 8) * D_ORI + kx + tx] =
            __uint_as_float(f2tf(tile[tx][ty + j * 8]));
}

// ---------------------------------------------------------------------------
// Kernel A: fused GEMM + relu + alpha projection.
//   acc = features @ attention_feat (tf32 mma), relu in registers,
//   then alpha partials = relu_acc @ alpha_w (fp32 FFMA) -> atomicAdd.
//   feat_off is NEVER written to global memory.
//   CTA tile 128x256, K=32 stages, 3-deep cp.async, warp tile 64x64.
// ---------------------------------------------------------------------------
#define BM 128
#define BN 256
#define BK 32
#define PAD 36
#define KITERS (D_ORI / BK)                 // 64
#define ASTG (BM * PAD)                     // 4608 floats
#define BSTG (BN * PAD)                     // 9216 floats
#define STG  (ASTG + BSTG)                  // 13824 floats
#define SMEM_GEMM_TOTAL (3 * STG * 4)       // 165888 bytes

__global__ __launch_bounds__(256, 1)
void gemm_alpha_kernel(const float* __restrict__ A,
                       const float* __restrict__ alpha_w,      // [G, 512, 4]
                       const float* __restrict__ alpha_w_cls)  // [G, 512, 1]
{
    extern __shared__ float smf[];
    const uint32_t sb = smem_u32(smf);
    const int tid  = threadIdx.x;
    const int wid  = tid >> 5;
    const int lane = tid & 31;
    const int r  = lane >> 2;
    const int cq = lane & 3;

    const int m0 = blockIdx.y * BM;
    const int n0 = blockIdx.x * BN;
    const int g  = blockIdx.y >> 5;          // 4096/128 = 32 M-tiles per g
    const int mbase = (wid & 1) * 64;
    const int nbase = (wid >> 1) * 64;

    const float* Abase = A + (size_t)m0 * D_ORI;
    const float* Bbase = g_Bt + (size_t)n0 * D_ORI;

    float acc[4][8][4];
#pragma unroll
    for (int mt = 0; mt < 4; mt++)
#pragma unroll
        for (int nt = 0; nt < 8; nt++)
#pragma unroll
            for (int i = 0; i < 4; i++) acc[mt][nt][i] = 0.f;

    auto load_stage = [&](int kiter, int slot) {
        const int k0 = kiter * BK;
        const uint32_t base = sb + slot * (STG * 4);
#pragma unroll
        for (int i = 0; i < 4; i++) {                 // A: 1024 x 16B
            int c = tid + i * 256;
            int row = c >> 3, kc = c & 7;
            CP_ASYNC16(base + row * (PAD * 4) + kc * 16,
                       Abase + (size_t)row * D_ORI + k0 + kc * 4);
        }
#pragma unroll
        for (int i = 0; i < 8; i++) {                 // B: 2048 x 16B
            int c = tid + i * 256;
            int row = c >> 3, kc = c & 7;
            CP_ASYNC16(base + ASTG * 4 + row * (PAD * 4) + kc * 16,
                       Bbase + (size_t)row * D_ORI + k0 + kc * 4);
        }
        CP_COMMIT();
    };

    load_stage(0, 0);
    load_stage(1, 1);

    for (int k = 0; k < KITERS; k++) {
        const int slot = k % 3;

        if (k < KITERS - 2) asm volatile("cp.async.wait_group 1;" ::: "memory");
        else                asm volatile("cp.async.wait_group 0;" ::: "memory");
        __syncthreads();

        if (k + 2 < KITERS) load_stage(k + 2, (k + 2) % 3);

        const float* As0 = smf + slot * STG;
        const float* Bs0 = As0 + ASTG;

#pragma unroll
        for (int kk = 0; kk < 4; kk++) {
            uint32_t af[4][4];
#pragma unroll
            for (int mt = 0; mt < 4; mt++) {
                const float* p = As0 + (mbase + mt * 16 + r) * PAD + kk * 8 + cq;
                af[mt][0] = f2tf(p[0]);
                af[mt][1] = f2tf(p[8 * PAD]);
                af[mt][2] = f2tf(p[4]);
                af[mt][3] = f2tf(p[8 * PAD + 4]);
            }
            uint32_t bf[8][2];
#pragma unroll
            for (int nt = 0; nt < 8; nt++) {
                const float* q = Bs0 + (nbase + nt * 8 + r) * PAD + kk * 8 + cq;
                bf[nt][0] = __float_as_uint(q[0]);   // pre-rounded tf32
                bf[nt][1] = __float_as_uint(q[4]);
            }
#pragma unroll
            for (int mt = 0; mt < 4; mt++)
#pragma unroll
                for (int nt = 0; nt < 8; nt++)
                    mma_tf32(acc[mt][nt], af[mt], bf[nt]);
        }
    }

    // ---- relu in registers ----
#pragma unroll
    for (int mt = 0; mt < 4; mt++)
#pragma unroll
        for (int nt = 0; nt < 8; nt++)
#pragma unroll
            for (int i = 0; i < 4; i++) acc[mt][nt][i] = fmaxf(acc[mt][nt][i], 0.f);

    // ---- stage alpha weights for this CTA's 256 columns ----
    __syncthreads();
    float* wA = smf;                          // reuse stage buffer: [256][6]
    {
        const int c = tid;                    // 256 threads == 256 cols
#pragma unroll
        for (int f = 0; f < 4; f++)
            wA[c * 6 + f] = alpha_w[((size_t)g * D_FEAT + n0 + c) * 4 + f];
        wA[c * 6 + 4] = alpha_w_cls[(size_t)g * D_FEAT + n0 + c];
    }
    __syncthreads();

    // ---- alpha partials: per thread, per owned row, dot over 16 owned cols ----
#pragma unroll
    for (int mt = 0; mt < 4; mt++) {
#pragma unroll
        for (int h = 0; h < 2; h++) {
            float s[5] = {0.f, 0.f, 0.f, 0.f, 0.f};
#pragma unroll
            for (int nt = 0; nt < 8; nt++) {
                const int col = nbase + nt * 8 + cq * 2;
                const float v0 = acc[mt][nt][2 * h + 0];
                const float v1 = acc[mt][nt][2 * h + 1];
#pragma unroll
                for (int f = 0; f < 5; f++)
                    s[f] += v0 * wA[col * 6 + f] + v1 * wA[(col + 1) * 6 + f];
            }
            // reduce over the 4 cq lanes (lanes 4r..4r+3)
#pragma unroll
            for (int f = 0; f < 5; f++) {
                s[f] += __shfl_xor_sync(0xFFFFFFFF, s[f], 1);
                s[f] += __shfl_xor_sync(0xFFFFFFFF, s[f], 2);
            }
            if (cq == 0) {
                const int grow = m0 + mbase + mt * 16 + h * 8 + r;
#pragma unroll
                for (int f = 0; f < 4; f++)
                    atomicAdd(&g_alpha[(size_t)grow * 4 + f], s[f]);
                atomicAdd(&g_alphacls[grow], s[4]);
            }
        }
    }
}

// ---------------------------------------------------------------------------
// Kernel B: branch GEMM via tf32 mma: per (g, 128-row tile):
//   [128 x 2048] @ [2048 x 32pad] -> offset(4) + cls(21).
//   A: 3-stage cp.async. W: register-prefetch + smem double buffer.
//   Epilogue: dpo add + cls softmax.
// ---------------------------------------------------------------------------
#define BASTG (128 * PAD)                         // 4608 floats per A stage
#define SMEM_BR_TOTAL ((3 * BASTG + 2 * 32 * PAD) * 4)   // 64512 bytes

__global__ __launch_bounds__(256, 1)
void branch_kernel(const float* __restrict__ feats,
                   const float* __restrict__ bbox_w,      // [G, D_ORI, 4]
                   const float* __restrict__ cls_w,       // [G, D_ORI, 21]
                   const float* __restrict__ delta_rois,  // [G, N, 5]
                   float* __restrict__ dpo_out,           // out1 [G,N,4]
                   float* __restrict__ cls_out)           // out2 [G,N,21]
{
    extern __shared__ float smf[];
    const uint32_t sb = smem_u32(smf);
    const int tid  = threadIdx.x;
    const int wid  = tid >> 5;
    const int lane = tid & 31;
    const int r  = lane >> 2;
    const int cq = lane & 3;

    const int g  = blockIdx.y;
    const int n0 = blockIdx.x * 128;

    const float* Abase = feats + ((size_t)g * N_PR + n0) * D_ORI;
    float* Wst = smf + 3 * BASTG;                 // [2][32][PAD]

    float acc[4][4];
#pragma unroll
    for (int nt = 0; nt < 4; nt++)
#pragma unroll
        for (int i = 0; i < 4; i++) acc[nt][i] = 0.f;

    auto wload = [&](int k0, float* wr) {
        const int col = lane;
#pragma unroll
        for (int i = 0; i < 4; i++) {
            const int d = k0 + (tid >> 5) + 8 * i;
            float w = 0.f;
            if (col < 4)       w = bbox_w[((size_t)g * D_ORI + d) * 4 + col];
            else if (col < 25) w = cls_w[((size_t)g * D_ORI + d) * 21 + col - 4];
            wr[i] = w;
        }
    };
    auto aload = [&](int kiter, int slot) {
        const uint32_t base = sb + slot * (BASTG * 4);
        const int k0 = kiter * BK;
#pragma unroll
        for (int i = 0; i < 4; i++) {
            int c = tid + i * 256;
            int row = c >> 3, kc = c & 7;
            CP_ASYNC16(base + row * (PAD * 4) + kc * 16,
                       Abase + (size_t)row * D_ORI + k0 + kc * 4);
        }
        CP_COMMIT();
    };

    float wreg[4];
    wload(0, wreg);
    aload(0, 0);
    aload(1, 1);

    for (int k = 0; k < KITERS; k++) {
        const int slot = k % 3;
        const int ws   = k & 1;

        if (k < KITERS - 2) asm volatile("cp.async.wait_group 1;" ::: "memory");
        else                asm volatile("cp.async.wait_group 0;" ::: "memory");

        // store prefetched weights (tf32-rounded) into smem buffer ws
        {
            const int col = lane;
            float* W = Wst + ws * 32 * PAD;
#pragma unroll
            for (int i = 0; i < 4; i++)
                W[col * PAD + (tid >> 5) + 8 * i] = __uint_as_float(f2tf(wreg[i]));
        }
        __syncthreads();

        if (k + 1 < KITERS) wload((k + 1) * BK, wreg);
        if (k + 2 < KITERS) aload(k + 2, (k + 2) % 3);

        const float* As0 = smf + slot * BASTG;
        const float* Ws0 = Wst + ws * 32 * PAD;

#pragma unroll
        for (int kk = 0; kk < 4; kk++) {
            uint32_t af[4];
            {
                const float* p = As0 + (wid * 16 + r) * PAD + kk * 8 + cq;
                af[0] = f2tf(p[0]);
                af[1] = f2tf(p[8 * PAD]);
                af[2] = f2tf(p[4]);
                af[3] = f2tf(p[8 * PAD + 4]);
            }
            uint32_t bf[4][2];
#pragma unroll
            for (int nt = 0; nt < 4; nt++) {
                const float* q = Ws0 + (nt * 8 + r) * PAD + kk * 8 + cq;
                bf[nt][0] = __float_as_uint(q[0]);
                bf[nt][1] = __float_as_uint(q[4]);
            }
#pragma unroll
            for (int nt = 0; nt < 4; nt++)
                mma_tf32(acc[nt], af, bf[nt]);
        }
        __syncthreads();
    }

    // ---- epilogue: stage logits to smem, then per-row softmax/dpo ----
    float* sT = smf;                              // [128][33]
#pragma unroll
    for (int nt = 0; nt < 4; nt++) {
        const int c0 = nt * 8 + cq * 2;
        const int r0 = wid * 16 + r;
        sT[r0 * 33 + c0]       = acc[nt][0];
        sT[r0 * 33 + c0 + 1]   = acc[nt][1];
        sT[(r0 + 8) * 33 + c0]     = acc[nt][2];
        sT[(r0 + 8) * 33 + c0 + 1] = acc[nt][3];
    }
    __syncthreads();

    if (tid < 128) {
        const int row = tid;
        const size_t gn = (size_t)g * N_PR + n0 + row;
        const float* L = sT + row * 33;

#pragma unroll
        for (int f = 0; f < 4; f++)
            dpo_out[gn * 4 + f] = delta_rois[gn * 5 + 1 + f] + L[f];

        float m = L[4];
#pragma unroll
        for (int c = 1; c < NCLS; c++) m = fmaxf(m, L[4 + c]);
        float e[NCLS], s = 0.f;
#pragma unroll
        for (int c = 0; c < NCLS; c++) {
            e[c] = expf(L[4 + c] - m);
            s += e[c];
        }
        const float inv = 1.f / s;
#pragma unroll
        for (int c = 0; c < NCLS; c++)
            cls_out[gn * NCLS + c] = e[c] * inv;
    }
}

// ---------------------------------------------------------------------------
// Kernel C: softmax over G + final weighted sum
// ---------------------------------------------------------------------------
__global__ void finalize_kernel(const float* __restrict__ dpo,
                                float* __restrict__ out0,
                                float* __restrict__ out3)
{
    int n = blockIdx.x * blockDim.x + threadIdx.x;
    if (n >= N_PR) return;

#pragma unroll
    for (int f = 0; f < 4; f++) {
        float a[G_SL];
        float m = -1e30f;
#pragma unroll
        for (int g = 0; g < G_SL; g++) {
            a[g] = g_alpha[((size_t)g * N_PR + n) * 4 + f];
            m = fmaxf(m, a[g]);
        }
        float s = 0.f;
#pragma unroll
        for (int g = 0; g < G_SL; g++) {
            a[g] = expf(a[g] - m);
            s += a[g];
        }
        float inv = 1.f / s;
        float o = 0.f;
#pragma unroll
        for (int g = 0; g < G_SL; g++)
            o += dpo[((size_t)g * N_PR + n) * 4 + f] * a[g] * inv;
        out0[(size_t)n * 4 + f] = o;
    }

    {
        float a[G_SL];
        float m = -1e30f;
#pragma unroll
        for (int g = 0; g < G_SL; g++) {
            a[g] = g_alphacls[(size_t)g * N_PR + n];
            m = fmaxf(m, a[g]);
        }
        float s = 0.f;
#pragma unroll
        for (int g = 0; g < G_SL; g++) {
            a[g] = expf(a[g] - m);
            s += a[g];
        }
        float inv = 1.f / s;
#pragma unroll
        for (int g = 0; g < G_SL; g++)
            out3[(size_t)g * N_PR + n] = a[g] * inv;
    }
}

// ---------------------------------------------------------------------------
// Launch
// ---------------------------------------------------------------------------
extern "C" void kernel_launch(void* const* d_in, const int* in_sizes, int n_in,
                              void* d_out, int out_size)
{
    const float* features     = (const float*)d_in[0];
    const float* delta_rois   = (const float*)d_in[3];
    const float* attention    = (const float*)d_in[5];
    const float* alpha_w      = (const float*)d_in[6];
    const float* bbox_regress = (const float*)d_in[7];
    const float* alpha_w_cls  = (const float*)d_in[8];
    const float* cls_w        = (const float*)d_in[9];

    float* out  = (float*)d_out;
    float* out0 = out;
    float* out1 = out + OFF1;
    float* out2 = out + OFF2;
    float* out3 = out + OFF3;

    static bool attr_set = false;
    if (!attr_set) {
        cudaFuncSetAttribute(gemm_alpha_kernel,
                             cudaFuncAttributeMaxDynamicSharedMemorySize,
                             SMEM_GEMM_TOTAL);
        cudaFuncSetAttribute(branch_kernel,
                             cudaFuncAttributeMaxDynamicSharedMemorySize,
                             SMEM_BR_TOTAL);
        attr_set = true;
    }

    // zero the atomic accumulators (graph-capturable)
    void* pA; cudaGetSymbolAddress(&pA, g_alpha);
    void* pC; cudaGetSymbolAddress(&pC, g_alphacls);
    cudaMemsetAsync(pA, 0, sizeof(float) * (size_t)M_TOT * 4, 0);
    cudaMemsetAsync(pC, 0, sizeof(float) * (size_t)M_TOT, 0);

    // transpose attention_feat to [N, K] (K-major, tf32-rounded)
    transpose_kernel<<<dim3(D_ORI / 32, D_FEAT / 32), dim3(32, 8)>>>(attention);

    // fused GEMM + relu + alpha projection (no feat_off materialization)
    gemm_alpha_kernel<<<dim3(D_FEAT / BN, M_TOT / BM), 256, SMEM_GEMM_TOTAL>>>(
        features, alpha_w, alpha_w_cls);

    // branch GEMM (offset + cls) + softmax + dpo
    branch_kernel<<<dim3(N_PR / 128, G_SL), 256, SMEM_BR_TOTAL>>>(
        features, bbox_regress, cls_w, delta_rois, out1, out2);

    // softmax over G + final output
    finalize_kernel<<<(N_PR + 255) / 256, 256>>>(out1, out0, out3);
}